// round 12
// baseline (speedup 1.0000x reference)
#include <cuda_runtime.h>
#include <cuda_fp16.h>
#include <cstdint>

// ---------------------------------------------------------------------------
// L2Attention via fp16 mma.sync (m16n8k16, fp32 accumulate).
// Fragment loads via ldmatrix.x4 (8x fewer LDS instructions).
// P stays in registers between score-MMA and PV-MMA (FA2 forwarding).
// b=4, n=1024, dim=1024, heads=16, d=64
// ---------------------------------------------------------------------------

#define M_ROWS 4096
#define DIM    1024

__device__ __half g_q [M_ROWS * DIM];
__device__ __half g_vt[M_ROWS * DIM];   // V transposed: [b][hd][token]
__device__ __half g_a [M_ROWS * DIM];
__device__ __half g_x [M_ROWS * DIM];
__device__ __half g_wq[DIM * DIM];
__device__ __half g_wv[DIM * DIM];
__device__ __half g_wo[DIM * DIM];
__device__ float  g_sq[64 * 1024];      // |q|^2 * 0.125 * log2(e)

#define C2EXP 0.36067376022224085f      // 2 * 0.125 * log2(e)

__device__ __forceinline__ float ex2(float x) {
    float r;
    asm("ex2.approx.f32 %0, %1;" : "=f"(r) : "f"(x));
    return r;
}
__device__ __forceinline__ uint32_t ldh2(const __half* p) {
    return *(const uint32_t*)p;
}
__device__ __forceinline__ uint32_t packh2(float lo, float hi) {
    __half2 h = __floats2half2_rn(lo, hi);
    return *(uint32_t*)&h;
}

// D += A(16x16) * B(16x8), fp16 inputs, fp32 accum
__device__ __forceinline__ void mma_f16(float c[4],
                                        uint32_t a0, uint32_t a1,
                                        uint32_t a2, uint32_t a3,
                                        uint32_t b0, uint32_t b1) {
    asm volatile(
        "mma.sync.aligned.m16n8k16.row.col.f32.f16.f16.f32 "
        "{%0,%1,%2,%3}, {%4,%5,%6,%7}, {%8,%9}, {%0,%1,%2,%3};\n"
        : "+f"(c[0]), "+f"(c[1]), "+f"(c[2]), "+f"(c[3])
        : "r"(a0), "r"(a1), "r"(a2), "r"(a3), "r"(b0), "r"(b1));
}

// 4x m8n8 b16 matrices; lanes 0-7/8-15/16-23/24-31 address matrices 0..3
__device__ __forceinline__ void ldsm4(uint32_t& r0, uint32_t& r1,
                                      uint32_t& r2, uint32_t& r3,
                                      uint32_t addr) {
    asm volatile(
        "ldmatrix.sync.aligned.m8n8.x4.shared.b16 {%0,%1,%2,%3}, [%4];"
        : "=r"(r0), "=r"(r1), "=r"(r2), "=r"(r3) : "r"(addr));
}

__device__ __forceinline__ void cp16(uint32_t smem_u32, const void* gptr) {
    asm volatile("cp.async.cg.shared.global [%0], [%1], 16;\n"
                 :: "r"(smem_u32), "l"(gptr));
}
#define CP_COMMIT() asm volatile("cp.async.commit_group;\n" ::: "memory")

// ---------------------------------------------------------------------------
// fp32 -> fp16 conversion: x (4M elems) + Wq/Wv/Wo (1M each)
// ---------------------------------------------------------------------------
__global__ __launch_bounds__(256) void conv_kernel(
    const float4* __restrict__ x,  __half* __restrict__ xo,
    const float4* __restrict__ w0, __half* __restrict__ w0o,
    const float4* __restrict__ w1, __half* __restrict__ w1o,
    const float4* __restrict__ w2, __half* __restrict__ w2o)
{
    int i = blockIdx.x * 256 + threadIdx.x;    // 8-elem units
    {
        float4 a = x[2 * i], b = x[2 * i + 1];
        uint4 u = { packh2(a.x, a.y), packh2(a.z, a.w),
                    packh2(b.x, b.y), packh2(b.z, b.w) };
        *(uint4*)(xo + 8 * (size_t)i) = u;
    }
    if (i < 131072) {
        float4 a = w0[2 * i], b = w0[2 * i + 1];
        uint4 u = { packh2(a.x, a.y), packh2(a.z, a.w),
                    packh2(b.x, b.y), packh2(b.z, b.w) };
        *(uint4*)(w0o + 8 * (size_t)i) = u;
        a = w1[2 * i]; b = w1[2 * i + 1];
        uint4 v = { packh2(a.x, a.y), packh2(a.z, a.w),
                    packh2(b.x, b.y), packh2(b.z, b.w) };
        *(uint4*)(w1o + 8 * (size_t)i) = v;
        a = w2[2 * i]; b = w2[2 * i + 1];
        uint4 w = { packh2(a.x, a.y), packh2(a.z, a.w),
                    packh2(b.x, b.y), packh2(b.z, b.w) };
        *(uint4*)(w2o + 8 * (size_t)i) = w;
    }
}

// ---------------------------------------------------------------------------
// fp16 GEMM: C = A @ B^T + bias, fp32 accum; fragments via ldmatrix.x4.
// 256 thr, 8 warps (4M x 2N), tile 128x128, K-step 64, 2-stage cp.async.
// mode: 0 = fp32 out, 1 = fp16 out + fused |q|^2 table, 2 = fp16 transposed.
// ---------------------------------------------------------------------------
#define SH 72                          // smem row stride in halves
#define G_STAGE_H (2 * 128 * SH)
#define STB (G_STAGE_H * 2)            // stage bytes
#define GEMM_SMEM (2 * G_STAGE_H * 2)  // 73728 bytes

__device__ __forceinline__ void g_load(
    uint32_t sb, int st, const __half* __restrict__ A,
    const __half* __restrict__ B, int bm, int bn, int k0, int t)
{
    uint32_t ab = sb + st * STB;
    uint32_t bb = ab + 128 * SH * 2;
#pragma unroll
    for (int l = 0; l < 4; l++) {
        int idx = t + l * 256;
        int r = idx >> 3, c = (idx & 7) * 8;
        cp16(ab + (r * SH + c) * 2, A + (size_t)(bm + r) * DIM + k0 + c);
    }
#pragma unroll
    for (int l = 0; l < 4; l++) {
        int idx = t + l * 256;
        int r = idx >> 3, c = (idx & 7) * 8;
        cp16(bb + (r * SH + c) * 2, B + (size_t)(bn + r) * DIM + k0 + c);
    }
    CP_COMMIT();
}

__global__ __launch_bounds__(256, 2) void gemm_f16_kernel(
    const __half* __restrict__ A,
    const __half* __restrict__ B0, const float* __restrict__ bias0,
    void* C0, int mode0,
    const __half* __restrict__ B1, const float* __restrict__ bias1,
    void* C1, int mode1,
    float* __restrict__ sqg)
{
    extern __shared__ __half smh[];
    const uint32_t sb = (uint32_t)__cvta_generic_to_shared(smh);

    const __half* B    = blockIdx.z ? B1 : B0;
    const float*  bias = blockIdx.z ? bias1 : bias0;
    void*         C    = blockIdx.z ? C1 : C0;
    const int     mode = blockIdx.z ? mode1 : mode0;

    const int t    = threadIdx.x;
    const int w    = t >> 5;
    const int lane = t & 31;
    const int g    = lane >> 2;
    const int tq   = lane & 3;
    const int wm   = w & 3;
    const int wn   = w >> 2;
    const int bm   = blockIdx.y * 128;
    const int bn   = blockIdx.x * 128;

    // ldmatrix per-lane offsets: lanes 0-7 -> m0, 8-15 -> m1(+8 rows),
    // 16-23 -> m2(+8 k), 24-31 -> m3(+8 rows, +8 k)
    const int lr  = (lane & 7) + ((lane >> 3) & 1) * 8;
    const int lk  = (lane >> 4) * 8;
    const uint32_t aoff = (uint32_t)((wm * 32 + lr) * SH + lk) * 2;
    const uint32_t boff = (uint32_t)(128 * SH + (wn * 64 + lr) * SH + lk) * 2;

    float acc[2][8][4];
#pragma unroll
    for (int i = 0; i < 2; i++)
#pragma unroll
        for (int j = 0; j < 8; j++)
#pragma unroll
            for (int r = 0; r < 4; r++) acc[i][j][r] = 0.f;

    g_load(sb, 0, A, B, bm, bn, 0, t);

    for (int it = 0; it < 16; it++) {
        const int cur = it & 1;
        asm volatile("cp.async.wait_group 0;\n" ::: "memory");
        __syncthreads();
        if (it + 1 < 16)
            g_load(sb, cur ^ 1, A, B, bm, bn, (it + 1) * 64, t);

        const uint32_t stg = sb + cur * STB;

#pragma unroll
        for (int ks = 0; ks < 4; ks++) {
            const uint32_t kkb = ks * 32;   // 16 halves = 32 bytes
            uint32_t a[2][4], b[8][2];
#pragma unroll
            for (int i = 0; i < 2; i++)
                ldsm4(a[i][0], a[i][1], a[i][2], a[i][3],
                      stg + aoff + i * (16 * SH * 2) + kkb);
#pragma unroll
            for (int jp = 0; jp < 4; jp++) {
                uint32_t r0, r1, r2, r3;
                ldsm4(r0, r1, r2, r3, stg + boff + jp * (16 * SH * 2) + kkb);
                b[2 * jp][0] = r0; b[2 * jp + 1][0] = r1;
                b[2 * jp][1] = r2; b[2 * jp + 1][1] = r3;
            }
#pragma unroll
            for (int i = 0; i < 2; i++)
#pragma unroll
                for (int j = 0; j < 8; j++)
                    mma_f16(acc[i][j], a[i][0], a[i][1], a[i][2], a[i][3],
                            b[j][0], b[j][1]);
        }
    }

    if (mode == 0) {
        float* Cf = (float*)C;
#pragma unroll
        for (int i = 0; i < 2; i++) {
            int row0 = bm + wm * 32 + i * 16 + g;
#pragma unroll
            for (int j = 0; j < 8; j++) {
                int col0 = bn + wn * 64 + j * 8 + 2 * tq;
                float b0 = bias[col0], b1 = bias[col0 + 1];
                *(float2*)(Cf + (size_t)row0 * DIM + col0) =
                    make_float2(acc[i][j][0] + b0, acc[i][j][1] + b1);
                *(float2*)(Cf + (size_t)(row0 + 8) * DIM + col0) =
                    make_float2(acc[i][j][2] + b0, acc[i][j][3] + b1);
            }
        }
    } else if (mode == 1) {
        __half* Ch = (__half*)C;
        float ss[2][2] = {{0.f, 0.f}, {0.f, 0.f}};
#pragma unroll
        for (int i = 0; i < 2; i++) {
            int row0 = bm + wm * 32 + i * 16 + g;
#pragma unroll
            for (int j = 0; j < 8; j++) {
                int col0 = bn + wn * 64 + j * 8 + 2 * tq;
                float b0 = bias[col0], b1 = bias[col0 + 1];
                uint32_t hl = packh2(acc[i][j][0] + b0, acc[i][j][1] + b1);
                uint32_t hh = packh2(acc[i][j][2] + b0, acc[i][j][3] + b1);
                *(uint32_t*)(Ch + (size_t)row0 * DIM + col0)       = hl;
                *(uint32_t*)(Ch + (size_t)(row0 + 8) * DIM + col0) = hh;
                float2 fl = __half22float2(*(__half2*)&hl);
                float2 fh = __half22float2(*(__half2*)&hh);
                ss[i][0] += fl.x * fl.x + fl.y * fl.y;
                ss[i][1] += fh.x * fh.x + fh.y * fh.y;
            }
        }
        // quad-reduce over tq -> full 64-dim head sum; head = warp's column band
#pragma unroll
        for (int i = 0; i < 2; i++)
#pragma unroll
            for (int hf = 0; hf < 2; hf++) {
                ss[i][hf] += __shfl_xor_sync(0xffffffffu, ss[i][hf], 1);
                ss[i][hf] += __shfl_xor_sync(0xffffffffu, ss[i][hf], 2);
            }
        if (tq == 0) {
            int hd = (bn >> 6) + wn;                  // head index
#pragma unroll
            for (int i = 0; i < 2; i++) {
                int r0 = bm + wm * 32 + i * 16 + g;
                int bb0 = r0 >> 10, n0 = r0 & 1023;
                sqg[(bb0 * 16 + hd) * 1024 + n0]       = ss[i][0] * (0.5f * C2EXP);
                sqg[(bb0 * 16 + hd) * 1024 + n0 + 8]   = ss[i][1] * (0.5f * C2EXP);
            }
        }
    } else {
        // transposed epilogue via smem: write C^T tile to g_vt[b][hd][token]
        __syncthreads();
        __half* T = smh;           // [128 cols][128 rows], stride 136
#pragma unroll
        for (int i = 0; i < 2; i++) {
            int rl = wm * 32 + i * 16 + g;
#pragma unroll
            for (int j = 0; j < 8; j++) {
                int cl = wn * 64 + j * 8 + 2 * tq;
                float b0 = bias[bn + cl], b1 = bias[bn + cl + 1];
                T[cl * 136 + rl]           = __float2half_rn(acc[i][j][0] + b0);
                T[(cl + 1) * 136 + rl]     = __float2half_rn(acc[i][j][1] + b1);
                T[cl * 136 + rl + 8]       = __float2half_rn(acc[i][j][2] + b0);
                T[(cl + 1) * 136 + rl + 8] = __float2half_rn(acc[i][j][3] + b1);
            }
        }
        __syncthreads();
        __half* Ch = (__half*)C;
        const int b    = bm >> 10;
        const int tokb = bm & 1023;
#pragma unroll
        for (int l = 0; l < 8; l++) {
            int idx = t + l * 256;
            int r = idx >> 4, c = (idx & 15) * 8;
            uint4 u = *(const uint4*)(T + r * 136 + c);
            *(uint4*)(Ch + ((size_t)(b * 1024 + bn + r)) * 1024 + tokb + c) = u;
        }
    }
}

// ---------------------------------------------------------------------------
// Fused attention (fp16 MMA, ldmatrix fragments, register-resident P):
// 128-query tile, 8 warps x 16 rows, 2 CTAs/SM, 2-stage 64-key ring.
// p = exp2(qk*C2 - si' - sj'); scores <= ~0 -> softmax w/o running max.
// ---------------------------------------------------------------------------
#define KST (64 * SH)
#define VST (64 * SH)
#define OFF_K  0
#define OFF_V  (2 * KST)            // 9216
#define OFF_S  (OFF_V + 2 * VST)    // 18432: Q staging only (prologue)
#define SQ_H   (OFF_S + 128 * SH)   // 27648 halves; float table after
#define ATT_BYTES (SQ_H * 2 + 4096) // 59392 B

__device__ __forceinline__ void a_load(
    uint32_t sb, int s, const __half* __restrict__ qb,
    const __half* __restrict__ vtb, int key0, int t)
{
#pragma unroll
    for (int l = 0; l < 2; l++) {
        int idx = t + l * 256;
        int r = idx >> 3, c = (idx & 7) * 8;
        cp16(sb + (OFF_K + s * KST + r * SH + c) * 2,
             qb + (size_t)(key0 + r) * DIM + c);
    }
#pragma unroll
    for (int l = 0; l < 2; l++) {
        int idx = t + l * 256;
        int r = idx >> 3, c = (idx & 7) * 8;
        cp16(sb + (OFF_V + s * VST + r * SH + c) * 2,
             vtb + (size_t)r * 1024 + key0 + c);
    }
    CP_COMMIT();
}

__global__ __launch_bounds__(256, 2) void attn_f16_kernel(
    const __half* __restrict__ q, const __half* __restrict__ vt,
    const float* __restrict__ sqg, __half* __restrict__ o)
{
    extern __shared__ __half smh[];
    const uint32_t sb = (uint32_t)__cvta_generic_to_shared(smh);

    const int bh = blockIdx.y;
    const int b  = bh >> 4;
    const int h  = bh & 15;
    const int qt = blockIdx.x * 128;
    const int t    = threadIdx.x;
    const int w    = t >> 5;
    const int lane = t & 31;
    const int g    = lane >> 2;
    const int tq   = lane & 3;
    const int i0   = 16 * w;

    // ldmatrix per-lane offset (rows x SH layout)
    const int lr = (lane & 7) + ((lane >> 3) & 1) * 8;
    const int lk = (lane >> 4) * 8;
    const uint32_t lmoff = (uint32_t)(lr * SH + lk) * 2;

    const __half* qbase  = q + ((size_t)b * 1024) * DIM + h * 64;
    const __half* vtbase = vt + ((size_t)(b * 1024 + h * 64)) * 1024;

    a_load(sb, 0, qbase, vtbase, 0, t);
    a_load(sb, 1, qbase, vtbase, 64, t);

    float* sqa = (float*)(smh + SQ_H);
    ((float4*)sqa)[t] = ((const float4*)(sqg + (size_t)bh * 1024))[t];

    // stage Q tile (transient) and pull fragments
    __half* Qs = smh + OFF_S;
#pragma unroll
    for (int l = 0; l < 4; l++) {
        int idx = t + l * 256;
        int r = idx >> 3, c = (idx & 7) * 8;
        *(uint4*)(Qs + r * SH + c) =
            *(const uint4*)(qbase + (size_t)(qt + r) * DIM + c);
    }
    __syncthreads();

    uint32_t qa[4][4];
    {
        const uint32_t qadr = sb + (uint32_t)(OFF_S + i0 * SH) * 2 + lmoff;
#pragma unroll
        for (int ks = 0; ks < 4; ks++)
            ldsm4(qa[ks][0], qa[ks][1], qa[ks][2], qa[ks][3], qadr + ks * 32);
    }
    const float nsi_lo = -sqa[qt + i0 + g];
    const float nsi_hi = -sqa[qt + i0 + 8 + g];
    __syncthreads();

    float oacc[8][4];
#pragma unroll
    for (int j = 0; j < 8; j++)
#pragma unroll
        for (int r = 0; r < 4; r++) oacc[j][r] = 0.f;
    float den_lo = 0.f, den_hi = 0.f;

    for (int it = 0; it < 16; it++) {
        const int s = it & 1;
        if (it < 15)
            asm volatile("cp.async.wait_group 1;\n" ::: "memory");
        else
            asm volatile("cp.async.wait_group 0;\n" ::: "memory");
        __syncthreads();

        const uint32_t kstg = sb + (uint32_t)(OFF_K + s * KST) * 2 + lmoff;
        const uint32_t vstg = sb + (uint32_t)(OFF_V + s * VST) * 2 + lmoff;
        const float*   sqk  = sqa + it * 64;

        float c[4][4];
        uint32_t p[8];

        // ---- scores chunk 0 (keys 0..31) ----
#pragma unroll
        for (int jj = 0; jj < 4; jj++)
#pragma unroll
            for (int r = 0; r < 4; r++) c[jj][r] = 0.f;
#pragma unroll
        for (int ks = 0; ks < 4; ks++) {
            uint32_t r0, r1, r2, r3, s0, s1, s2, s3;
            ldsm4(r0, r1, r2, r3, kstg + ks * 32);                 // keys 0-15
            ldsm4(s0, s1, s2, s3, kstg + 16 * SH * 2 + ks * 32);   // keys 16-31
            mma_f16(c[0], qa[ks][0], qa[ks][1], qa[ks][2], qa[ks][3], r0, r2);
            mma_f16(c[1], qa[ks][0], qa[ks][1], qa[ks][2], qa[ks][3], r1, r3);
            mma_f16(c[2], qa[ks][0], qa[ks][1], qa[ks][2], qa[ks][3], s0, s2);
            mma_f16(c[3], qa[ks][0], qa[ks][1], qa[ks][2], qa[ks][3], s1, s3);
        }

#pragma unroll
        for (int jc = 0; jc < 2; jc++) {
            const int par = jc * 32;

            // ---- softmax(jc): c -> p (register fragments) ----
#pragma unroll
            for (int jj = 0; jj < 4; jj++) {
                int cb = jj * 8 + 2 * tq;
                float2 sj = *(const float2*)(sqk + par + cb);
                float p00 = ex2(fmaf(c[jj][0], C2EXP, nsi_lo - sj.x));
                float p01 = ex2(fmaf(c[jj][1], C2EXP, nsi_lo - sj.y));
                float p10 = ex2(fmaf(c[jj][2], C2EXP, nsi_hi - sj.x));
                float p11 = ex2(fmaf(c[jj][3], C2EXP, nsi_hi - sj.y));
                uint32_t hl = packh2(p00, p01);
                uint32_t hh = packh2(p10, p11);
                float2 fl = __half22float2(*(__half2*)&hl);
                float2 fh = __half22float2(*(__half2*)&hh);
                den_lo += fl.x + fl.y;
                den_hi += fh.x + fh.y;
                p[2 * jj]     = hl;
                p[2 * jj + 1] = hh;
            }

            // ---- scores(jc+1) while tensor pipe drains ----
            if (jc < 1) {
#pragma unroll
                for (int jj = 0; jj < 4; jj++)
#pragma unroll
                    for (int r = 0; r < 4; r++) c[jj][r] = 0.f;
#pragma unroll
                for (int ks = 0; ks < 4; ks++) {
                    uint32_t r0, r1, r2, r3, s0, s1, s2, s3;
                    ldsm4(r0, r1, r2, r3, kstg + 32 * SH * 2 + ks * 32);
                    ldsm4(s0, s1, s2, s3, kstg + 48 * SH * 2 + ks * 32);
                    mma_f16(c[0], qa[ks][0], qa[ks][1], qa[ks][2], qa[ks][3], r0, r2);
                    mma_f16(c[1], qa[ks][0], qa[ks][1], qa[ks][2], qa[ks][3], r1, r3);
                    mma_f16(c[2], qa[ks][0], qa[ks][1], qa[ks][2], qa[ks][3], s0, s2);
                    mma_f16(c[3], qa[ks][0], qa[ks][1], qa[ks][2], qa[ks][3], s1, s3);
                }
            }

            // ---- PV(jc): A = P fragments, B = Vt via ldmatrix ----
#pragma unroll
            for (int ksl = 0; ksl < 2; ksl++) {
                uint32_t a0 = p[4 * ksl + 0];
                uint32_t a1 = p[4 * ksl + 1];
                uint32_t a2 = p[4 * ksl + 2];
                uint32_t a3 = p[4 * ksl + 3];
                const uint32_t vkey = (uint32_t)(par + ksl * 16) * 2;
#pragma unroll
                for (int jp = 0; jp < 4; jp++) {
                    uint32_t r0, r1, r2, r3;
                    ldsm4(r0, r1, r2, r3, vstg + jp * (16 * SH * 2) + vkey);
                    mma_f16(oacc[2 * jp],     a0, a1, a2, a3, r0, r2);
                    mma_f16(oacc[2 * jp + 1], a0, a1, a2, a3, r1, r3);
                }
            }
        }
        __syncthreads();

        if (it + 2 < 16)
            a_load(sb, s, qbase, vtbase, (it + 2) * 64, t);
    }

    den_lo += __shfl_xor_sync(0xffffffffu, den_lo, 1);
    den_lo += __shfl_xor_sync(0xffffffffu, den_lo, 2);
    den_hi += __shfl_xor_sync(0xffffffffu, den_hi, 1);
    den_hi += __shfl_xor_sync(0xffffffffu, den_hi, 2);
    const float inv_lo = 1.f / den_lo;
    const float inv_hi = 1.f / den_hi;

    __half* orow_lo = o + (size_t)(b * 1024 + qt + i0 + g) * DIM + h * 64;
    __half* orow_hi = o + (size_t)(b * 1024 + qt + i0 + 8 + g) * DIM + h * 64;
#pragma unroll
    for (int j = 0; j < 8; j++) {
        int col = j * 8 + 2 * tq;
        *(uint32_t*)(orow_lo + col) = packh2(oacc[j][0] * inv_lo,
                                             oacc[j][1] * inv_lo);
        *(uint32_t*)(orow_hi + col) = packh2(oacc[j][2] * inv_hi,
                                             oacc[j][3] * inv_hi);
    }
}

// ---------------------------------------------------------------------------
extern "C" void kernel_launch(void* const* d_in, const int* in_sizes, int n_in,
                              void* d_out, int out_size)
{
    const float* x  = (const float*)d_in[0];
    const float* Wq = (const float*)d_in[1];
    const float* bq = (const float*)d_in[2];
    const float* Wv = (const float*)d_in[3];
    const float* bv = (const float*)d_in[4];
    const float* Wo = (const float*)d_in[5];
    const float* bo = (const float*)d_in[6];
    float* out = (float*)d_out;

    __half *qp, *vtp, *ap, *xp, *wqp, *wvp, *wop;
    float* sqp;
    cudaGetSymbolAddress((void**)&qp,  g_q);
    cudaGetSymbolAddress((void**)&vtp, g_vt);
    cudaGetSymbolAddress((void**)&ap,  g_a);
    cudaGetSymbolAddress((void**)&xp,  g_x);
    cudaGetSymbolAddress((void**)&wqp, g_wq);
    cudaGetSymbolAddress((void**)&wvp, g_wv);
    cudaGetSymbolAddress((void**)&wop, g_wo);
    cudaGetSymbolAddress((void**)&sqp, g_sq);

    cudaFuncSetAttribute(gemm_f16_kernel,
                         cudaFuncAttributeMaxDynamicSharedMemorySize, GEMM_SMEM);
    cudaFuncSetAttribute(attn_f16_kernel,
                         cudaFuncAttributeMaxDynamicSharedMemorySize, ATT_BYTES);

    conv_kernel<<<2048, 256>>>(
        (const float4*)x,  xp,
        (const float4*)Wq, wqp,
        (const float4*)Wv, wvp,
        (const float4*)Wo, wop);

    // fused Q (half + |q|^2 table) + V (transposed half) projections
    gemm_f16_kernel<<<dim3(8, 32, 2), 256, GEMM_SMEM>>>(
        xp, wqp, bq, (void*)qp, 1, wvp, bv, (void*)vtp, 2, sqp);

    attn_f16_kernel<<<dim3(8, 64), 256, ATT_BYTES>>>(qp, vtp, sqp, ap);

    gemm_f16_kernel<<<dim3(8, 32, 1), 256, GEMM_SMEM>>>(
        ap, wop, bo, (void*)out, 0, wop, bo, (void*)out, 0, sqp);
}